// round 12
// baseline (speedup 1.0000x reference)
#include <cuda_runtime.h>
#include <cstdint>

// out[c,t,x,y] = mc ? k[t] : mp ? 0.5*k[t-1] : mn ? 0.25*k[t+1] : 0   (cases exclusive)
// Mask is channel-invariant -> precompute 2-bit selector per (t, xy) into a
// 1 MB L2-resident quad-major table sel4[q][g] (uint4, q = t/16; component
// word w packs t = 16q+4w .. 16q+4w+3; 4 lanes * 2 bits per t).
// Main kernel: pure 1-load/1-store rolling stream; 1024-thread CTAs spanning
// 1024 consecutive float4-groups (16 KB contiguous per t-access) for DRAM
// row locality. PDL with sync at kernel top hides the launch gap.

#define ALPHA 0.5f
#define BETA  0.25f

constexpr int NC  = 32;
constexpr int NT  = 64;
constexpr int PLANE4 = 256 * 256 / 4;   // 16384 float4 groups per t-slice
constexpr int COLS   = NC * PLANE4;     // 524288 stream threads
constexpr int NQUAD  = NT / 16;         // 4 uint4 selector quads per g
constexpr int TPB    = 1024;            // stream CTA size
constexpr int NCTA   = COLS / TPB;      // 512

__device__ uint4 g_sel4[NQUAD * PLANE4];  // [quad q][g], 1 MB

__device__ __forceinline__ uint32_t code1(int mc, int mp, int mn) {
    return mc ? 1u : (mp ? 2u : (mn ? 3u : 0u));
}

// One thread per (half h, g), h = 0..7: computes 8 t-steps (t = 8h..8h+7),
// stores them as the (h&1 ? .zw : .xy) half of g_sel4[(h>>1)*PLANE4 + g].
__global__ void __launch_bounds__(256)
pre_kernel(const int4* __restrict__ mask)
{
    const int tidg = blockIdx.x * blockDim.x + threadIdx.x;  // 0 .. 8*PLANE4-1
    const int g = tidg & (PLANE4 - 1);
    const int h = tidg >> 14;            // 0..7
    const int t0 = h * 8;

    int4 mbuf[10];
    #pragma unroll
    for (int i = 0; i < 10; i++) {
        const int t = t0 - 1 + i;
        mbuf[i] = (t >= 0 && t < NT) ? __ldg(&mask[t * PLANE4 + g])
                                     : make_int4(0, 0, 0, 0);
    }

    uint32_t w[2] = {0u, 0u};
    #pragma unroll
    for (int i = 0; i < 8; i++) {
        const int4 mp = mbuf[i];
        const int4 mc = mbuf[i + 1];
        const int4 mn = mbuf[i + 2];
        uint32_t byte =  code1(mc.x, mp.x, mn.x)
                      | (code1(mc.y, mp.y, mn.y) << 2)
                      | (code1(mc.z, mp.z, mn.z) << 4)
                      | (code1(mc.w, mp.w, mn.w) << 6);
        w[i >> 2] |= byte << ((i & 3) * 8);
    }

    // 8-byte store into the proper half of the uint4 slot
    uint2* half_ptr = reinterpret_cast<uint2*>(&g_sel4[(h >> 1) * PLANE4 + g])
                    + (h & 1);
    *half_ptr = make_uint2(w[0], w[1]);

#if __CUDA_ARCH__ >= 900
    cudaTriggerProgrammaticLaunchCompletion();
#endif
}

__device__ __forceinline__ float pick(uint32_t c, float kc, float kp, float kn) {
    return (c == 1u) ? kc
         : (c == 2u) ? ALPHA * kp
         : (c == 3u) ? BETA * kn
         : 0.0f;
}

__global__ void __launch_bounds__(TPB)
dsb_kernel(const float4* __restrict__ k, float4* __restrict__ out)
{
#if __CUDA_ARCH__ >= 900
    cudaGridDependencySynchronize();     // before any memory traffic
#endif

    const int gid = blockIdx.x * TPB + threadIdx.x;
    const int g = gid & (PLANE4 - 1);
    const int c = gid >> 14;

    const float4* kk = k   + (size_t)c * NT * PLANE4 + g;
    float4*       oo = out + (size_t)c * NT * PLANE4 + g;

    float4 kp = make_float4(0.f, 0.f, 0.f, 0.f);
    float4 kc = __ldcs(kk);

    int t = 0;
    #pragma unroll 1
    for (int q = 0; q < NQUAD; q++) {
        const uint4 s = __ldg(&g_sel4[q * PLANE4 + g]);   // L2-resident, 16B
        uint32_t words[4] = { s.x, s.y, s.z, s.w };
        #pragma unroll
        for (int j = 0; j < 4; j++) {
            const uint32_t wrd = words[j];
            #pragma unroll
            for (int tt = 0; tt < 4; tt++) {
                float4 kn = (t < NT - 1) ? __ldcs(kk + (t + 1) * PLANE4)
                                         : make_float4(0.f, 0.f, 0.f, 0.f);

                const uint32_t byte = (wrd >> (tt * 8)) & 0xFFu;
                float4 o;
                o.x = pick( byte       & 3u, kc.x, kp.x, kn.x);
                o.y = pick((byte >> 2) & 3u, kc.y, kp.y, kn.y);
                o.z = pick((byte >> 4) & 3u, kc.z, kp.z, kn.z);
                o.w = pick((byte >> 6) & 3u, kc.w, kp.w, kn.w);

                __stcs(oo + t * PLANE4, o);

                kp = kc; kc = kn;
                t++;
            }
        }
    }
}

extern "C" void kernel_launch(void* const* d_in, const int* in_sizes, int n_in,
                              void* d_out, int out_size)
{
    const float4* k    = (const float4*)d_in[0];
    const int4*   mask = (const int4*)d_in[1];
    float4*       out  = (float4*)d_out;

    pre_kernel<<<(8 * PLANE4) / 256, 256>>>(mask);

    cudaLaunchConfig_t cfg = {};
    cfg.gridDim  = dim3(NCTA);
    cfg.blockDim = dim3(TPB);
    cfg.dynamicSmemBytes = 0;
    cfg.stream = 0;
    cudaLaunchAttribute attr[1];
    attr[0].id = cudaLaunchAttributeProgrammaticStreamSerialization;
    attr[0].val.programmaticStreamSerializationAllowed = 1;
    cfg.attrs = attr;
    cfg.numAttrs = 1;
    cudaError_t err = cudaLaunchKernelEx(&cfg, dsb_kernel, k, out);
    if (err != cudaSuccess) {
        dsb_kernel<<<NCTA, TPB>>>(k, out);
    }
}

// round 13
// speedup vs baseline: 1.3205x; 1.3205x over previous
#include <cuda_runtime.h>
#include <cstdint>

// out[c,t,x,y] = mc ? k[t] : mp ? 0.5*k[t-1] : mn ? 0.25*k[t+1] : 0   (cases exclusive)
// Mask is channel-invariant -> precompute 2-bit selector per (t, xy) into a
// 1 MB L2-resident word-major table sel[w][g] (uint32, w = t/4; packs
// t = 4w..4w+3, 4 lanes * 2 bits per t).
// Main kernel: pure 1-load/1-store rolling stream; 512-thread CTAs spanning
// 512 consecutive float4-groups (8 KB contiguous per t-access). PDL with
// sync at kernel top hides the launch gap.

#define ALPHA 0.5f
#define BETA  0.25f

constexpr int NC  = 32;
constexpr int NT  = 64;
constexpr int PLANE4 = 256 * 256 / 4;   // 16384 float4 groups per t-slice
constexpr int COLS   = NC * PLANE4;     // 524288 stream threads
constexpr int NW     = NT / 4;          // 16 selector words per g
constexpr int TPB    = 512;             // stream CTA size
constexpr int NCTA   = COLS / TPB;      // 1024

__device__ uint32_t g_sel[NW * PLANE4];   // [word w][g], 1 MB

__device__ __forceinline__ uint32_t code1(int mc, int mp, int mn) {
    return mc ? 1u : (mp ? 2u : (mn ? 3u : 0u));
}

// One thread per (word w, g): computes 4 t-steps (t = 4w..4w+3).
// 6 coalesced int4 loads, 1 fully-coalesced 4B store.
__global__ void __launch_bounds__(256)
pre_kernel(const int4* __restrict__ mask)
{
    const int tidg = blockIdx.x * blockDim.x + threadIdx.x;  // 0 .. NW*PLANE4-1
    const int g = tidg & (PLANE4 - 1);
    const int w = tidg >> 14;            // 0..15
    const int t0 = w * 4;

    int4 mbuf[6];
    #pragma unroll
    for (int i = 0; i < 6; i++) {
        const int t = t0 - 1 + i;
        mbuf[i] = (t >= 0 && t < NT) ? __ldg(&mask[t * PLANE4 + g])
                                     : make_int4(0, 0, 0, 0);
    }

    uint32_t word = 0u;
    #pragma unroll
    for (int i = 0; i < 4; i++) {
        const int4 mp = mbuf[i];
        const int4 mc = mbuf[i + 1];
        const int4 mn = mbuf[i + 2];
        uint32_t byte =  code1(mc.x, mp.x, mn.x)
                      | (code1(mc.y, mp.y, mn.y) << 2)
                      | (code1(mc.z, mp.z, mn.z) << 4)
                      | (code1(mc.w, mp.w, mn.w) << 6);
        word |= byte << (i * 8);
    }

    g_sel[w * PLANE4 + g] = word;

#if __CUDA_ARCH__ >= 900
    cudaTriggerProgrammaticLaunchCompletion();
#endif
}

__device__ __forceinline__ float pick(uint32_t c, float kc, float kp, float kn) {
    return (c == 1u) ? kc
         : (c == 2u) ? ALPHA * kp
         : (c == 3u) ? BETA * kn
         : 0.0f;
}

__global__ void __launch_bounds__(TPB, 4)
dsb_kernel(const float4* __restrict__ k, float4* __restrict__ out)
{
#if __CUDA_ARCH__ >= 900
    cudaGridDependencySynchronize();     // before any memory traffic
#endif

    const int gid = blockIdx.x * TPB + threadIdx.x;
    const int g = gid & (PLANE4 - 1);
    const int c = gid >> 14;

    const float4* kk = k   + (size_t)c * NT * PLANE4 + g;
    float4*       oo = out + (size_t)c * NT * PLANE4 + g;

    float4 kp = make_float4(0.f, 0.f, 0.f, 0.f);
    float4 kc = __ldcs(kk);

    int t = 0;
    #pragma unroll 1
    for (int w = 0; w < NW; w++) {
        const uint32_t wrd = __ldg(&g_sel[w * PLANE4 + g]);   // L2-resident
        #pragma unroll
        for (int tt = 0; tt < 4; tt++) {
            float4 kn = (t < NT - 1) ? __ldcs(kk + (t + 1) * PLANE4)
                                     : make_float4(0.f, 0.f, 0.f, 0.f);

            const uint32_t byte = (wrd >> (tt * 8)) & 0xFFu;
            float4 o;
            o.x = pick( byte       & 3u, kc.x, kp.x, kn.x);
            o.y = pick((byte >> 2) & 3u, kc.y, kp.y, kn.y);
            o.z = pick((byte >> 4) & 3u, kc.z, kp.z, kn.z);
            o.w = pick((byte >> 6) & 3u, kc.w, kp.w, kn.w);

            __stcs(oo + t * PLANE4, o);

            kp = kc; kc = kn;
            t++;
        }
    }
}

extern "C" void kernel_launch(void* const* d_in, const int* in_sizes, int n_in,
                              void* d_out, int out_size)
{
    const float4* k    = (const float4*)d_in[0];
    const int4*   mask = (const int4*)d_in[1];
    float4*       out  = (float4*)d_out;

    pre_kernel<<<(NW * PLANE4) / 256, 256>>>(mask);

    cudaLaunchConfig_t cfg = {};
    cfg.gridDim  = dim3(NCTA);
    cfg.blockDim = dim3(TPB);
    cfg.dynamicSmemBytes = 0;
    cfg.stream = 0;
    cudaLaunchAttribute attr[1];
    attr[0].id = cudaLaunchAttributeProgrammaticStreamSerialization;
    attr[0].val.programmaticStreamSerializationAllowed = 1;
    cfg.attrs = attr;
    cfg.numAttrs = 1;
    cudaError_t err = cudaLaunchKernelEx(&cfg, dsb_kernel, k, out);
    if (err != cudaSuccess) {
        dsb_kernel<<<NCTA, TPB>>>(k, out);
    }
}

// round 14
// speedup vs baseline: 1.3209x; 1.0004x over previous
#include <cuda_runtime.h>
#include <cstdint>

// out[c,t,x,y] = mc ? k[t] : mp ? 0.5*k[t-1] : mn ? 0.25*k[t+1] : 0   (cases exclusive)
// Mask is channel-invariant -> precompute 2-bit selector per (t, xy) into a
// 1 MB L2-resident word-major table sel[w][g] (uint32, w = t/4; packs
// t = 4w..4w+3, 4 lanes * 2 bits per t).
// Main kernel: pure 1-load/1-store rolling stream; 512-thread CTAs spanning
// 512 consecutive float4-groups (8 KB contiguous per t-access), 32 regs
// (exactly full RF at occ 4). Plain sequential launches (PDL measured as a
// net cost here).

#define ALPHA 0.5f
#define BETA  0.25f

constexpr int NC  = 32;
constexpr int NT  = 64;
constexpr int PLANE4 = 256 * 256 / 4;   // 16384 float4 groups per t-slice
constexpr int COLS   = NC * PLANE4;     // 524288 stream threads
constexpr int NW     = NT / 4;          // 16 selector words per g
constexpr int TPB    = 512;             // stream CTA size
constexpr int NCTA   = COLS / TPB;      // 1024

__device__ uint32_t g_sel[NW * PLANE4];   // [word w][g], 1 MB

__device__ __forceinline__ uint32_t code1(int mc, int mp, int mn) {
    return mc ? 1u : (mp ? 2u : (mn ? 3u : 0u));
}

// One thread per (word w, g): computes 4 t-steps (t = 4w..4w+3).
// 6 coalesced int4 loads, 1 fully-coalesced 4B store.
__global__ void __launch_bounds__(256)
pre_kernel(const int4* __restrict__ mask)
{
    const int tidg = blockIdx.x * blockDim.x + threadIdx.x;  // 0 .. NW*PLANE4-1
    const int g = tidg & (PLANE4 - 1);
    const int w = tidg >> 14;            // 0..15
    const int t0 = w * 4;

    int4 mbuf[6];
    #pragma unroll
    for (int i = 0; i < 6; i++) {
        const int t = t0 - 1 + i;
        mbuf[i] = (t >= 0 && t < NT) ? __ldg(&mask[t * PLANE4 + g])
                                     : make_int4(0, 0, 0, 0);
    }

    uint32_t word = 0u;
    #pragma unroll
    for (int i = 0; i < 4; i++) {
        const int4 mp = mbuf[i];
        const int4 mc = mbuf[i + 1];
        const int4 mn = mbuf[i + 2];
        uint32_t byte =  code1(mc.x, mp.x, mn.x)
                      | (code1(mc.y, mp.y, mn.y) << 2)
                      | (code1(mc.z, mp.z, mn.z) << 4)
                      | (code1(mc.w, mp.w, mn.w) << 6);
        word |= byte << (i * 8);
    }

    g_sel[w * PLANE4 + g] = word;
}

__device__ __forceinline__ float pick(uint32_t c, float kc, float kp, float kn) {
    return (c == 1u) ? kc
         : (c == 2u) ? ALPHA * kp
         : (c == 3u) ? BETA * kn
         : 0.0f;
}

__global__ void __launch_bounds__(TPB, 4)
dsb_kernel(const float4* __restrict__ k, float4* __restrict__ out)
{
    const int gid = blockIdx.x * TPB + threadIdx.x;
    const int g = gid & (PLANE4 - 1);
    const int c = gid >> 14;

    const float4* kk = k   + (size_t)c * NT * PLANE4 + g;
    float4*       oo = out + (size_t)c * NT * PLANE4 + g;

    float4 kp = make_float4(0.f, 0.f, 0.f, 0.f);
    float4 kc = __ldcs(kk);

    int t = 0;
    #pragma unroll 1
    for (int w = 0; w < NW; w++) {
        const uint32_t wrd = __ldg(&g_sel[w * PLANE4 + g]);   // L2-resident
        #pragma unroll
        for (int tt = 0; tt < 4; tt++) {
            float4 kn = (t < NT - 1) ? __ldcs(kk + (t + 1) * PLANE4)
                                     : make_float4(0.f, 0.f, 0.f, 0.f);

            const uint32_t byte = (wrd >> (tt * 8)) & 0xFFu;
            float4 o;
            o.x = pick( byte       & 3u, kc.x, kp.x, kn.x);
            o.y = pick((byte >> 2) & 3u, kc.y, kp.y, kn.y);
            o.z = pick((byte >> 4) & 3u, kc.z, kp.z, kn.z);
            o.w = pick((byte >> 6) & 3u, kc.w, kp.w, kn.w);

            __stcs(oo + t * PLANE4, o);

            kp = kc; kc = kn;
            t++;
        }
    }
}

extern "C" void kernel_launch(void* const* d_in, const int* in_sizes, int n_in,
                              void* d_out, int out_size)
{
    const float4* k    = (const float4*)d_in[0];
    const int4*   mask = (const int4*)d_in[1];
    float4*       out  = (float4*)d_out;

    pre_kernel<<<(NW * PLANE4) / 256, 256>>>(mask);
    dsb_kernel<<<NCTA, TPB>>>(k, out);
}

// round 15
// speedup vs baseline: 1.3214x; 1.0004x over previous
#include <cuda_runtime.h>
#include <cstdint>

// out[c,t,x,y] = mc ? k[t] : mp ? 0.5*k[t-1] : mn ? 0.25*k[t+1] : 0   (cases exclusive)
// Mask is channel-invariant -> precompute 2-bit selector per (t, xy) into a
// 1 MB L2-resident word-major table sel[w][g] (uint32, w = t/4; packs
// t = 4w..4w+3, 4 lanes * 2 bits per t).
// Main kernel: pure 1-load/1-store rolling stream; 512-thread CTAs spanning
// 512 consecutive float4-groups (8 KB contiguous per t-access), 32 regs
// (exactly full RF at occ 4). Plain sequential launches (PDL measured as a
// net cost here).

#define ALPHA 0.5f
#define BETA  0.25f

constexpr int NC  = 32;
constexpr int NT  = 64;
constexpr int PLANE4 = 256 * 256 / 4;   // 16384 float4 groups per t-slice
constexpr int COLS   = NC * PLANE4;     // 524288 stream threads
constexpr int NW     = NT / 4;          // 16 selector words per g
constexpr int TPB    = 512;             // stream CTA size
constexpr int NCTA   = COLS / TPB;      // 1024

__device__ uint32_t g_sel[NW * PLANE4];   // [word w][g], 1 MB

__device__ __forceinline__ uint32_t code1(int mc, int mp, int mn) {
    return mc ? 1u : (mp ? 2u : (mn ? 3u : 0u));
}

// One thread per (word w, g): computes 4 t-steps (t = 4w..4w+3).
// 6 coalesced int4 loads, 1 fully-coalesced 4B store.
__global__ void __launch_bounds__(256)
pre_kernel(const int4* __restrict__ mask)
{
    const int tidg = blockIdx.x * blockDim.x + threadIdx.x;  // 0 .. NW*PLANE4-1
    const int g = tidg & (PLANE4 - 1);
    const int w = tidg >> 14;            // 0..15
    const int t0 = w * 4;

    int4 mbuf[6];
    #pragma unroll
    for (int i = 0; i < 6; i++) {
        const int t = t0 - 1 + i;
        mbuf[i] = (t >= 0 && t < NT) ? __ldg(&mask[t * PLANE4 + g])
                                     : make_int4(0, 0, 0, 0);
    }

    uint32_t word = 0u;
    #pragma unroll
    for (int i = 0; i < 4; i++) {
        const int4 mp = mbuf[i];
        const int4 mc = mbuf[i + 1];
        const int4 mn = mbuf[i + 2];
        uint32_t byte =  code1(mc.x, mp.x, mn.x)
                      | (code1(mc.y, mp.y, mn.y) << 2)
                      | (code1(mc.z, mp.z, mn.z) << 4)
                      | (code1(mc.w, mp.w, mn.w) << 6);
        word |= byte << (i * 8);
    }

    g_sel[w * PLANE4 + g] = word;
}

__device__ __forceinline__ float pick(uint32_t c, float kc, float kp, float kn) {
    return (c == 1u) ? kc
         : (c == 2u) ? ALPHA * kp
         : (c == 3u) ? BETA * kn
         : 0.0f;
}

__global__ void __launch_bounds__(TPB, 4)
dsb_kernel(const float4* __restrict__ k, float4* __restrict__ out)
{
    const int gid = blockIdx.x * TPB + threadIdx.x;
    const int g = gid & (PLANE4 - 1);
    const int c = gid >> 14;

    const float4* kk = k   + (size_t)c * NT * PLANE4 + g;
    float4*       oo = out + (size_t)c * NT * PLANE4 + g;

    float4 kp = make_float4(0.f, 0.f, 0.f, 0.f);
    float4 kc = __ldcs(kk);

    int t = 0;
    #pragma unroll 1
    for (int w = 0; w < NW; w++) {
        const uint32_t wrd = __ldg(&g_sel[w * PLANE4 + g]);   // L2-resident
        #pragma unroll
        for (int tt = 0; tt < 4; tt++) {
            float4 kn = (t < NT - 1) ? __ldcs(kk + (t + 1) * PLANE4)
                                     : make_float4(0.f, 0.f, 0.f, 0.f);

            const uint32_t byte = (wrd >> (tt * 8)) & 0xFFu;
            float4 o;
            o.x = pick( byte       & 3u, kc.x, kp.x, kn.x);
            o.y = pick((byte >> 2) & 3u, kc.y, kp.y, kn.y);
            o.z = pick((byte >> 4) & 3u, kc.z, kp.z, kn.z);
            o.w = pick((byte >> 6) & 3u, kc.w, kp.w, kn.w);

            __stcs(oo + t * PLANE4, o);

            kp = kc; kc = kn;
            t++;
        }
    }
}

extern "C" void kernel_launch(void* const* d_in, const int* in_sizes, int n_in,
                              void* d_out, int out_size)
{
    const float4* k    = (const float4*)d_in[0];
    const int4*   mask = (const int4*)d_in[1];
    float4*       out  = (float4*)d_out;

    pre_kernel<<<(NW * PLANE4) / 256, 256>>>(mask);
    dsb_kernel<<<NCTA, TPB>>>(k, out);
}